// round 2
// baseline (speedup 1.0000x reference)
#include <cuda_runtime.h>
#include <math.h>

#define EPS 1e-8f
// B=64, S=64, I=64, O=64, N=1024, M=64, H=256, 4H=1024, P=268

// Persistent NTM memory, stored TRANSPOSED: memT[b][m][n], 64 x 64 x 1024 floats = 16 MB
__device__ float g_memT[64ull * 64 * 1024];

__device__ __forceinline__ float sigmoidf_(float x) { return 1.f / (1.f + expf(-x)); }
__device__ __forceinline__ float softplusf_(float x) { return fmaxf(x, 0.f) + log1pf(expf(-fabsf(x))); }

// Block reduction of two values across 1024 threads. MAX=true -> max, else sum.
template <bool MAX>
__device__ __forceinline__ float2 blockReduce2(float2 v, float2* red) {
#pragma unroll
    for (int o = 16; o; o >>= 1) {
        float ox = __shfl_xor_sync(0xffffffffu, v.x, o);
        float oy = __shfl_xor_sync(0xffffffffu, v.y, o);
        if (MAX) { v.x = fmaxf(v.x, ox); v.y = fmaxf(v.y, oy); }
        else     { v.x += ox;            v.y += oy; }
    }
    int w = threadIdx.x >> 5;
    if ((threadIdx.x & 31) == 0) red[w] = v;
    __syncthreads();
    if (threadIdx.x < 32) {
        v = red[threadIdx.x];
#pragma unroll
        for (int o = 16; o; o >>= 1) {
            float ox = __shfl_xor_sync(0xffffffffu, v.x, o);
            float oy = __shfl_xor_sync(0xffffffffu, v.y, o);
            if (MAX) { v.x = fmaxf(v.x, ox); v.y = fmaxf(v.y, oy); }
            else     { v.x += ox;            v.y += oy; }
        }
        if (threadIdx.x == 0) red[0] = v;
    }
    __syncthreads();
    v = red[0];
    __syncthreads();   // allow scratch reuse by subsequent call
    return v;
}

__global__ void __launch_bounds__(1024, 1)
ntm_kernel(const float* __restrict__ x,       // (64,64,64)
           const float* __restrict__ Wx,      // (128,1024)
           const float* __restrict__ Wh,      // (256,1024)
           const float* __restrict__ b_lstm,  // (1024)
           const float* __restrict__ W_head,  // (256,268)
           const float* __restrict__ b_head,  // (268)
           const float* __restrict__ W_out,   // (320,64)
           const float* __restrict__ b_out,   // (64)
           float* __restrict__ out)           // (64,64,64)
{
    const int b = blockIdx.x;
    const int t = threadIdx.x;

    __shared__ __align__(16) float s_xr[128];
    __shared__ __align__(16) float s_h[256];
    __shared__ __align__(16) float s_c[256];
    __shared__ __align__(16) float s_r[64];
    __shared__ __align__(16) float s_gates[1024];
    __shared__ __align__(16) float s_p[272];
    __shared__ __align__(16) float s_kr[64];
    __shared__ __align__(16) float s_kw[64];
    __shared__ __align__(16) float s_e[64];
    __shared__ __align__(16) float s_a[64];
    __shared__ __align__(16) float s_wr[1024];
    __shared__ __align__(16) float s_ww[1024];
    __shared__ __align__(16) float s_t1[1024];
    __shared__ __align__(16) float s_t2[1024];
    __shared__ __align__(16) float4 s_part[1024];   // GEMV partials (reused as float scratch)
    __shared__ float2 s_red[32];
    __shared__ float s_scal[16];
    // s_scal: [0]=beta_r [1]=g_r [2..4]=s_r [5]=gamma_r [6]=||k_r||
    //         [8]=beta_w [9]=g_w [10..12]=s_w [13]=gamma_w [14]=||k_w||

    float* mem = g_memT + (size_t)b * 65536;       // [m][n]
    float4* mem4 = (float4*)mem;                    // element (m, n4) at mem4[m*256 + n4]
    float* s_partf = (float*)s_part;

    // ---- init state (re-done every launch: deterministic) ----
    {
        float4 iv = make_float4(0.01f, 0.01f, 0.01f, 0.01f);
#pragma unroll
        for (int i = 0; i < 16; ++i) mem4[i * 1024 + t] = iv;   // 16384 float4 total
        float w0 = (t == 0) ? 1.f : 0.f;
        s_wr[t] = w0;
        s_ww[t] = w0;
        if (t < 256) { s_h[t] = 0.f; s_c[t] = 0.f; }
        if (t < 64) s_r[t] = 0.f;
    }
    __syncthreads();

    for (int step = 0; step < 64; ++step) {
        // ---- phase 1: xr = [x_t, r] ----
        if (t < 64) s_xr[t] = x[((b << 6) + step) * 64 + t];
        else if (t < 128) s_xr[t] = s_r[t - 64];
        __syncthreads();

        // ---- phase 2: gates = xr@Wx + h@Wh (1024 outputs, 4 row-chunks of 96) ----
        {
            int q = t & 255;        // output quad: columns 4q..4q+3
            int ch = t >> 8;        // row chunk 0..3
            const float4* wx4 = (const float4*)Wx;
            const float4* wh4 = (const float4*)Wh;
            float4 acc = make_float4(0.f, 0.f, 0.f, 0.f);
            int r0 = ch * 32;
#pragma unroll 4
            for (int r = r0; r < r0 + 32; ++r) {
                float xv = s_xr[r];
                float4 w = wx4[r * 256 + q];
                acc.x += xv * w.x; acc.y += xv * w.y; acc.z += xv * w.z; acc.w += xv * w.w;
            }
            int h0 = ch * 64;
#pragma unroll 4
            for (int r = h0; r < h0 + 64; ++r) {
                float hv = s_h[r];
                float4 w = wh4[r * 256 + q];
                acc.x += hv * w.x; acc.y += hv * w.y; acc.z += hv * w.z; acc.w += hv * w.w;
            }
            s_part[t] = acc;
        }
        __syncthreads();
        if (t < 256) {
            float4 a0 = s_part[t], a1 = s_part[t + 256], a2 = s_part[t + 512], a3 = s_part[t + 768];
            float4 bb = ((const float4*)b_lstm)[t];
            float4 g;
            g.x = a0.x + a1.x + a2.x + a3.x + bb.x;
            g.y = a0.y + a1.y + a2.y + a3.y + bb.y;
            g.z = a0.z + a1.z + a2.z + a3.z + bb.z;
            g.w = a0.w + a1.w + a2.w + a3.w + bb.w;
            ((float4*)s_gates)[t] = g;
        }
        __syncthreads();

        // ---- phase 3: LSTM pointwise; also zero r accumulator ----
        if (t < 256) {
            float ig = s_gates[t], fg = s_gates[256 + t], gg = s_gates[512 + t], og = s_gates[768 + t];
            float cc = sigmoidf_(fg) * s_c[t] + sigmoidf_(ig) * tanhf(gg);
            s_c[t] = cc;
            s_h[t] = sigmoidf_(og) * tanhf(cc);
        } else if (t < 320) {
            s_r[t - 256] = 0.f;
        }
        __syncthreads();

        // ---- phase 4: p = h @ W_head + b_head (268 outputs, 2 row-halves) ----
        if (t < 536) {
            int half = (t >= 268);
            int j = t - half * 268;
            int k0 = half * 128;
            float acc = 0.f;
#pragma unroll 8
            for (int k = k0; k < k0 + 128; ++k) acc += s_h[k] * W_head[k * 268 + j];
            s_partf[t] = acc;
        }
        __syncthreads();
        if (t < 268) s_p[t] = s_partf[t] + s_partf[t + 268] + b_head[t];
        __syncthreads();

        // ---- phase 5: parse heads ----
        if (t < 64) s_kr[t] = tanhf(s_p[t]);
        else if (t < 128) s_kw[t - 64] = tanhf(s_p[70 + (t - 64)]);
        else if (t < 192) s_e[t - 128] = sigmoidf_(s_p[140 + (t - 128)]);
        else if (t < 256) s_a[t - 192] = s_p[204 + (t - 192)];
        else if (t == 256) {
            s_scal[0] = softplusf_(s_p[64]);
            s_scal[1] = sigmoidf_(s_p[65]);
            float a0 = s_p[66], a1 = s_p[67], a2 = s_p[68];
            float mx = fmaxf(a0, fmaxf(a1, a2));
            float e0 = expf(a0 - mx), e1 = expf(a1 - mx), e2 = expf(a2 - mx);
            float sm = e0 + e1 + e2;
            s_scal[2] = e0 / sm; s_scal[3] = e1 / sm; s_scal[4] = e2 / sm;
            s_scal[5] = 1.f + softplusf_(s_p[69]);
        } else if (t == 288) {
            s_scal[8] = softplusf_(s_p[134]);
            s_scal[9] = sigmoidf_(s_p[135]);
            float a0 = s_p[136], a1 = s_p[137], a2 = s_p[138];
            float mx = fmaxf(a0, fmaxf(a1, a2));
            float e0 = expf(a0 - mx), e1 = expf(a1 - mx), e2 = expf(a2 - mx);
            float sm = e0 + e1 + e2;
            s_scal[10] = e0 / sm; s_scal[11] = e1 / sm; s_scal[12] = e2 / sm;
            s_scal[13] = 1.f + softplusf_(s_p[139]);
        }
        __syncthreads();
        // key norms (warp 0: k_r, warp 1: k_w)
        if (t < 32) {
            float v = s_kr[t] * s_kr[t] + s_kr[t + 32] * s_kr[t + 32];
#pragma unroll
            for (int o = 16; o; o >>= 1) v += __shfl_xor_sync(0xffffffffu, v, o);
            if (t == 0) s_scal[6] = sqrtf(v);
        } else if (t < 64) {
            int l = t - 32;
            float v = s_kw[l] * s_kw[l] + s_kw[l + 32] * s_kw[l + 32];
#pragma unroll
            for (int o = 16; o; o >>= 1) v += __shfl_xor_sync(0xffffffffu, v, o);
            if (l == 0) s_scal[14] = sqrtf(v);
        }
        __syncthreads();

        // ---- phase 6: addressing (thread t handles memory row n = t) ----
        float qr, qw;
        {
            float dr = 0.f, dw = 0.f, nn = 0.f;
#pragma unroll 8
            for (int m = 0; m < 64; ++m) {
                float v = mem[m * 1024 + t];
                dr += s_kr[m] * v;
                dw += s_kw[m] * v;
                nn += v * v;
            }
            float nrm = sqrtf(nn);
            qr = s_scal[0] * (dr / (s_scal[6]  * nrm + EPS));
            qw = s_scal[8] * (dw / (s_scal[14] * nrm + EPS));
        }
        float2 mx = blockReduce2<true>(make_float2(qr, qw), s_red);
        float er = expf(qr - mx.x), ew = expf(qw - mx.y);
        float2 sm = blockReduce2<false>(make_float2(er, ew), s_red);
        float wcr = er / sm.x, wcw = ew / sm.y;
        float wgr = s_scal[1] * wcr + (1.f - s_scal[1]) * s_wr[t];
        float wgw = s_scal[9] * wcw + (1.f - s_scal[9]) * s_ww[t];
        s_t1[t] = wgr;
        s_t2[t] = wgw;
        __syncthreads();
        {
            int np = (t + 1) & 1023, nm = (t + 1023) & 1023;
            float wsr = s_scal[2]  * s_t1[np] + s_scal[3]  * s_t1[t] + s_scal[4]  * s_t1[nm];
            float wsw = s_scal[10] * s_t2[np] + s_scal[11] * s_t2[t] + s_scal[12] * s_t2[nm];
            float wpr = (wsr > 0.f) ? expf(s_scal[5]  * logf(wsr)) : 0.f;
            float wpw = (wsw > 0.f) ? expf(s_scal[13] * logf(wsw)) : 0.f;
            float2 sp = blockReduce2<false>(make_float2(wpr, wpw), s_red);
            s_wr[t] = wpr / (sp.x + EPS);
            s_ww[t] = wpw / (sp.y + EPS);
        }
        __syncthreads();

        // ---- phase 7: r = w_r @ mem (old), mem erase/add update (fused) ----
        {
            int n4 = t & 255;            // float4 group over n
            int m0 = (t >> 8) * 16;      // 16 m-rows per thread
            float4 wr4 = ((const float4*)s_wr)[n4];
            float4 ww4 = ((const float4*)s_ww)[n4];
#pragma unroll 4
            for (int mi = 0; mi < 16; ++mi) {
                int m = m0 + mi;
                float em = s_e[m], am = s_a[m];
                float4 v = mem4[m * 256 + n4];
                float rp = wr4.x * v.x + wr4.y * v.y + wr4.z * v.z + wr4.w * v.w;
                v.x = v.x * (1.f - ww4.x * em) + ww4.x * am;
                v.y = v.y * (1.f - ww4.y * em) + ww4.y * am;
                v.z = v.z * (1.f - ww4.z * em) + ww4.z * am;
                v.w = v.w * (1.f - ww4.w * em) + ww4.w * am;
                mem4[m * 256 + n4] = v;
#pragma unroll
                for (int o = 16; o; o >>= 1) rp += __shfl_xor_sync(0xffffffffu, rp, o);
                if ((t & 31) == 0) atomicAdd(&s_r[m], rp);
            }
        }
        __syncthreads();

        // ---- phase 8: out = [h, r] @ W_out + b_out (64 outputs, 16 row-chunks of 20) ----
        {
            int o = t & 63;
            int ch = t >> 6;
            int r0 = ch * 20;
            float acc = 0.f;
#pragma unroll
            for (int rr = r0; rr < r0 + 20; ++rr) {
                float v = (rr < 256) ? s_h[rr] : s_r[rr - 256];
                acc += v * W_out[rr * 64 + o];
            }
            s_partf[t] = acc;
        }
        __syncthreads();
        if (t < 64) {
            float acc = b_out[t];
#pragma unroll
            for (int ch = 0; ch < 16; ++ch) acc += s_partf[t + ch * 64];
            out[((b << 6) + step) * 64 + t] = acc;
        }
        __syncthreads();
    }
}

extern "C" void kernel_launch(void* const* d_in, const int* in_sizes, int n_in,
                              void* d_out, int out_size) {
    const float* x      = (const float*)d_in[0];
    const float* Wx     = (const float*)d_in[1];
    const float* Wh     = (const float*)d_in[2];
    const float* b_lstm = (const float*)d_in[3];
    const float* W_head = (const float*)d_in[4];
    const float* b_head = (const float*)d_in[5];
    const float* W_out  = (const float*)d_in[6];
    const float* b_out  = (const float*)d_in[7];
    float* out = (float*)d_out;
    ntm_kernel<<<64, 1024>>>(x, Wx, Wh, b_lstm, W_head, b_head, W_out, b_out, out);
}

// round 3
// speedup vs baseline: 1.2695x; 1.2695x over previous
#include <cuda_runtime.h>
#include <cooperative_groups.h>
#include <math.h>

namespace cg = cooperative_groups;

#define EPS 1e-8f
// B=64, S=64, I=64, O=64, N=1024, M=64, H=256, 4H=1024, P=268
// 2-CTA cluster per batch: rank r owns n in [512r,512r+512), h in [128r,128r+128),
// gate cols {gb*256+128r .. +128}, p cols [134r,134r+134), out cols [32r,32r+32).

struct SMem {
    float  mem[64 * 512];   // NTM memory half, [m][nl]  (128 KB)
    float4 part[1024];      // GEMV partials / addressing partials (16 KB)
    float  wr[512], ww[512];
    float  t1[516], t2[516];  // wg + halo slots 512 (peer nl=0), 513 (peer nl=511)
    float  h[2][256];         // double-buffered full hidden state
    float  c[128];            // own c half
    float  xr[128];
    float  gates[512];        // own gate columns: [gb*128 + jl]
    float  p[144];            // own p chunk (134)
    float  kr[64], kw[64], e[64], a[64];
    float  rvec[64], rpart[64], rpeer[64];
    float  scal[16];          // 0..5 read-head, 6=|kr|,7=|kw|, 8..13 write-head
    float  xch[8];            // cross-CTA reduction slots (peer writes here)
    float2 red[32];
};

__device__ __forceinline__ float sigmoidf_(float x) { return 1.f / (1.f + expf(-x)); }
__device__ __forceinline__ float softplusf_(float x) { return fmaxf(x, 0.f) + log1pf(expf(-fabsf(x))); }

template <bool MAX>
__device__ __forceinline__ float2 blockReduce2(float2 v, float2* red) {
#pragma unroll
    for (int o = 16; o; o >>= 1) {
        float ox = __shfl_xor_sync(0xffffffffu, v.x, o);
        float oy = __shfl_xor_sync(0xffffffffu, v.y, o);
        if (MAX) { v.x = fmaxf(v.x, ox); v.y = fmaxf(v.y, oy); }
        else     { v.x += ox;            v.y += oy; }
    }
    int w = threadIdx.x >> 5;
    if ((threadIdx.x & 31) == 0) red[w] = v;
    __syncthreads();
    if (threadIdx.x < 32) {
        v = red[threadIdx.x];
#pragma unroll
        for (int o = 16; o; o >>= 1) {
            float ox = __shfl_xor_sync(0xffffffffu, v.x, o);
            float oy = __shfl_xor_sync(0xffffffffu, v.y, o);
            if (MAX) { v.x = fmaxf(v.x, ox); v.y = fmaxf(v.y, oy); }
            else     { v.x += ox;            v.y += oy; }
        }
        if (threadIdx.x == 0) red[0] = v;
    }
    __syncthreads();
    v = red[0];
    __syncthreads();
    return v;
}

__global__ void __launch_bounds__(1024, 1) __cluster_dims__(2, 1, 1)
ntm_kernel(const float* __restrict__ x,       // (64,64,64)
           const float* __restrict__ Wx,      // (128,1024)
           const float* __restrict__ Wh,      // (256,1024)
           const float* __restrict__ b_lstm,  // (1024)
           const float* __restrict__ W_head,  // (256,268)
           const float* __restrict__ b_head,  // (268)
           const float* __restrict__ W_out,   // (320,64)
           const float* __restrict__ b_out,   // (64)
           float* __restrict__ out)           // (64,64,64)
{
    extern __shared__ char smraw[];
    SMem* s = (SMem*)smraw;
    cg::cluster_group cl = cg::this_cluster();

    const int rank = blockIdx.x & 1;
    const int b    = blockIdx.x >> 1;
    const int t    = threadIdx.x;

    SMem* ps = cl.map_shared_rank(s, rank ^ 1);

    float*  partf = (float*)s->part;
    float4* mem4  = (float4*)s->mem;

    // ---- init ----
    {
        float4 iv = make_float4(0.01f, 0.01f, 0.01f, 0.01f);
#pragma unroll
        for (int i = 0; i < 8; ++i) mem4[i * 1024 + t] = iv;  // 8192 quads = 64*512 floats
        if (t < 512) { float w0 = (rank == 0 && t == 0) ? 1.f : 0.f; s->wr[t] = w0; s->ww[t] = w0; }
        if (t < 256) { s->h[0][t] = 0.f; s->h[1][t] = 0.f; }
        if (t < 128) s->c[t] = 0.f;
        if (t < 64)  s->rvec[t] = 0.f;
    }
    cl.sync();

    for (int step = 0; step < 64; ++step) {
        const int cur = step & 1, prv = cur ^ 1;
        float* hn = s->h[cur];
        const float* hp = s->h[prv];

        // ---- phase 1: xr = [x_t, r] ----
        if (t < 64) s->xr[t] = x[((b << 6) + step) * 64 + t];
        else if (t < 128) s->xr[t] = s->rvec[t - 64];
        __syncthreads();

        // ---- phase 2: own 512 gate columns = xr@Wx + h@Wh ----
        {
            int q4 = t & 31, gb = (t >> 5) & 3, ch = t >> 7;   // ch 0..7
            int col4 = gb * 64 + rank * 32 + q4;
            const float4* wx4 = (const float4*)Wx;
            const float4* wh4 = (const float4*)Wh;
            float4 acc = make_float4(0.f, 0.f, 0.f, 0.f);
            int r0 = ch * 48;
#pragma unroll 4
            for (int r = r0; r < r0 + 48; ++r) {
                float  v = (r < 128) ? s->xr[r] : hp[r - 128];
                float4 w = (r < 128) ? wx4[r * 256 + col4] : wh4[(r - 128) * 256 + col4];
                acc.x += v * w.x; acc.y += v * w.y; acc.z += v * w.z; acc.w += v * w.w;
            }
            s->part[t] = acc;
        }
        __syncthreads();
        if (t < 128) {
            int col4 = (t >> 5) * 64 + rank * 32 + (t & 31);
            float4 acc = ((const float4*)b_lstm)[col4];
#pragma unroll
            for (int ch = 0; ch < 8; ++ch) {
                float4 p0 = s->part[t + 128 * ch];
                acc.x += p0.x; acc.y += p0.y; acc.z += p0.z; acc.w += p0.w;
            }
            ((float4*)s->gates)[t] = acc;
        }
        __syncthreads();

        // ---- phase 3: LSTM pointwise on own h half; publish to both CTAs ----
        if (t < 128) {
            float ig = s->gates[t], fg = s->gates[128 + t],
                  gg = s->gates[256 + t], og = s->gates[384 + t];
            float cc = sigmoidf_(fg) * s->c[t] + sigmoidf_(ig) * tanhf(gg);
            s->c[t] = cc;
            float hv = sigmoidf_(og) * tanhf(cc);
            int gj = rank * 128 + t;
            hn[gj] = hv;
            ps->h[cur][gj] = hv;
        }
        cl.sync();   // A: full new h visible in both CTAs

        // ---- phase 4: own 134 head outputs ----
        if (t < 536) {
            int j = t % 134, ch = t / 134;     // ch 0..3
            int col = 134 * rank + j;
            float acc = 0.f;
            int k0 = ch * 64;
#pragma unroll 8
            for (int k = k0; k < k0 + 64; ++k) acc += hn[k] * W_head[k * 268 + col];
            partf[t] = acc;
        }
        if (t >= 960) s->rpart[t - 960] = 0.f;   // zero r accumulator for this step
        __syncthreads();
        if (t < 134) s->p[t] = partf[t] + partf[t + 134] + partf[t + 268] + partf[t + 402]
                               + b_head[134 * rank + t];
        __syncthreads();

        // ---- phase 5: parse heads, exchange shares ----
        if (rank == 0) {
            // owns p_g[0:134] = pr(70) + kw(64)
            if (t < 64)       { float v = tanhf(s->p[t]);           s->kr[t] = v;      ps->kr[t] = v; }
            else if (t < 128) { float v = tanhf(s->p[70 + t - 64]); s->kw[t - 64] = v; ps->kw[t - 64] = v; }
            else if (t == 128) {
                float v0 = softplusf_(s->p[64]);
                float v1 = sigmoidf_(s->p[65]);
                float a0 = s->p[66], a1 = s->p[67], a2 = s->p[68];
                float mx = fmaxf(a0, fmaxf(a1, a2));
                float e0 = expf(a0 - mx), e1 = expf(a1 - mx), e2 = expf(a2 - mx);
                float sm = e0 + e1 + e2;
                float v5 = 1.f + softplusf_(s->p[69]);
                s->scal[0] = v0; ps->scal[0] = v0;
                s->scal[1] = v1; ps->scal[1] = v1;
                s->scal[2] = e0 / sm; ps->scal[2] = e0 / sm;
                s->scal[3] = e1 / sm; ps->scal[3] = e1 / sm;
                s->scal[4] = e2 / sm; ps->scal[4] = e2 / sm;
                s->scal[5] = v5; ps->scal[5] = v5;
            }
            __syncthreads();
            if (t < 32) {
                float v = s->kr[t] * s->kr[t] + s->kr[t + 32] * s->kr[t + 32];
#pragma unroll
                for (int o = 16; o; o >>= 1) v += __shfl_xor_sync(0xffffffffu, v, o);
                if (t == 0) { float nr = sqrtf(v); s->scal[6] = nr; ps->scal[6] = nr; }
            } else if (t < 64) {
                int l = t - 32;
                float v = s->kw[l] * s->kw[l] + s->kw[l + 32] * s->kw[l + 32];
#pragma unroll
                for (int o = 16; o; o >>= 1) v += __shfl_xor_sync(0xffffffffu, v, o);
                if (l == 0) { float nw = sqrtf(v); s->scal[7] = nw; ps->scal[7] = nw; }
            }
        } else {
            // owns p_g[134:268]: write-head scalars(6) + e(64) + a(64)
            if (t < 64)       { float v = sigmoidf_(s->p[6 + t]); s->e[t] = v;      ps->e[t] = v; }
            else if (t < 128) { float v = s->p[70 + t - 64];      s->a[t - 64] = v; ps->a[t - 64] = v; }
            else if (t == 128) {
                float v0 = softplusf_(s->p[0]);
                float v1 = sigmoidf_(s->p[1]);
                float a0 = s->p[2], a1 = s->p[3], a2 = s->p[4];
                float mx = fmaxf(a0, fmaxf(a1, a2));
                float e0 = expf(a0 - mx), e1 = expf(a1 - mx), e2 = expf(a2 - mx);
                float sm = e0 + e1 + e2;
                float v5 = 1.f + softplusf_(s->p[5]);
                s->scal[8]  = v0; ps->scal[8]  = v0;
                s->scal[9]  = v1; ps->scal[9]  = v1;
                s->scal[10] = e0 / sm; ps->scal[10] = e0 / sm;
                s->scal[11] = e1 / sm; ps->scal[11] = e1 / sm;
                s->scal[12] = e2 / sm; ps->scal[12] = e2 / sm;
                s->scal[13] = v5; ps->scal[13] = v5;
            }
            __syncthreads();
        }
        cl.sync();   // B: kr,kw,e,a,scal complete on both CTAs

        // ---- phase 6: addressing over own 512 n-rows (mem in SMEM) ----
        const int nl = t & 511, mh = t >> 9;
        {
            float dr = 0.f, dw = 0.f, nn = 0.f;
            int m0 = mh * 32;
#pragma unroll 8
            for (int m = m0; m < m0 + 32; ++m) {
                float v = s->mem[m * 512 + nl];
                dr += s->kr[m] * v;
                dw += s->kw[m] * v;
                nn += v * v;
            }
            s->part[t] = make_float4(dr, dw, nn, 0.f);
        }
        __syncthreads();
        float qr = -1e30f, qw = -1e30f;
        const bool lead = (t < 512);
        if (lead) {
            float4 p0 = s->part[t], p1 = s->part[t + 512];
            float dr = p0.x + p1.x, dw = p0.y + p1.y, nn = p0.z + p1.z;
            float nrm = sqrtf(nn);
            qr = s->scal[0] * (dr / (s->scal[6] * nrm + EPS));
            qw = s->scal[8] * (dw / (s->scal[7] * nrm + EPS));
        }
        float2 lmax = blockReduce2<true>(make_float2(qr, qw), s->red);
        if (t == 0) { ps->xch[0] = lmax.x; ps->xch[1] = lmax.y; }
        cl.sync();   // C
        float gmx = fmaxf(lmax.x, s->xch[0]);
        float gmy = fmaxf(lmax.y, s->xch[1]);
        float er = lead ? expf(qr - gmx) : 0.f;
        float ew = lead ? expf(qw - gmy) : 0.f;
        float2 lsum = blockReduce2<false>(make_float2(er, ew), s->red);
        if (t == 0) { ps->xch[2] = lsum.x; ps->xch[3] = lsum.y; }
        cl.sync();   // D
        {
            float gsr = lsum.x + s->xch[2], gsw = lsum.y + s->xch[3];
            if (lead) {
                float wcr = er / gsr, wcw = ew / gsw;
                float wgr = s->scal[1] * wcr + (1.f - s->scal[1]) * s->wr[nl];
                float wgw = s->scal[9] * wcw + (1.f - s->scal[9]) * s->ww[nl];
                s->t1[nl] = wgr;
                s->t2[nl] = wgw;
                if (nl == 0)   { ps->t1[512] = wgr; ps->t2[512] = wgw; }
                if (nl == 511) { ps->t1[513] = wgr; ps->t2[513] = wgw; }
            }
        }
        cl.sync();   // E: wg + halos ready
        float wpr = 0.f, wpw = 0.f;
        if (lead) {
            int np = (nl == 511) ? 512 : nl + 1;
            int nm = (nl == 0)   ? 513 : nl - 1;
            float wsr = s->scal[2]  * s->t1[np] + s->scal[3]  * s->t1[nl] + s->scal[4]  * s->t1[nm];
            float wsw = s->scal[10] * s->t2[np] + s->scal[11] * s->t2[nl] + s->scal[12] * s->t2[nm];
            wpr = (wsr > 0.f) ? expf(s->scal[5]  * logf(wsr)) : 0.f;
            wpw = (wsw > 0.f) ? expf(s->scal[13] * logf(wsw)) : 0.f;
        }
        float2 lsp = blockReduce2<false>(make_float2(wpr, wpw), s->red);
        if (t == 0) { ps->xch[4] = lsp.x; ps->xch[5] = lsp.y; }
        cl.sync();   // F
        if (lead) {
            s->wr[nl] = wpr / ((lsp.x + s->xch[4]) + EPS);
            s->ww[nl] = wpw / ((lsp.y + s->xch[5]) + EPS);
        }
        __syncthreads();

        // ---- phase 7: fused read (old mem) + erase/add update, all in SMEM ----
        {
            int n4 = t & 127, mch = t >> 7;
            float4 wr4 = ((const float4*)s->wr)[n4];
            float4 ww4 = ((const float4*)s->ww)[n4];
#pragma unroll 4
            for (int mi = 0; mi < 8; ++mi) {
                int m = mch * 8 + mi;
                float em = s->e[m], am = s->a[m];
                float4 v = mem4[m * 128 + n4];
                float rp = wr4.x * v.x + wr4.y * v.y + wr4.z * v.z + wr4.w * v.w;
                v.x = v.x * (1.f - ww4.x * em) + ww4.x * am;
                v.y = v.y * (1.f - ww4.y * em) + ww4.y * am;
                v.z = v.z * (1.f - ww4.z * em) + ww4.z * am;
                v.w = v.w * (1.f - ww4.w * em) + ww4.w * am;
                mem4[m * 128 + n4] = v;
#pragma unroll
                for (int o = 16; o; o >>= 1) rp += __shfl_xor_sync(0xffffffffu, rp, o);
                if ((t & 31) == 0) atomicAdd(&s->rpart[m], rp);
            }
        }
        __syncthreads();
        if (t < 64) ps->rpeer[t] = s->rpart[t];
        cl.sync();   // G: r partials exchanged
        if (t < 64) s->rvec[t] = s->rpart[t] + s->rpeer[t];
        __syncthreads();

        // ---- phase 8: own 32 output columns = [h, r] @ W_out + b_out ----
        {
            int o = t & 31, ch = t >> 5;    // 32 chunks x 10 rows
            int col = rank * 32 + o;
            float acc = 0.f;
            int r0 = ch * 10;
#pragma unroll
            for (int rr = r0; rr < r0 + 10; ++rr) {
                float v = (rr < 256) ? hn[rr] : s->rvec[rr - 256];
                acc += v * W_out[rr * 64 + col];
            }
            partf[t] = acc;
        }
        __syncthreads();
        if (t < 32) {
            float acc = b_out[rank * 32 + t];
#pragma unroll
            for (int ch = 0; ch < 32; ++ch) acc += partf[t + 32 * ch];
            out[((b << 6) + step) * 64 + rank * 32 + t] = acc;
        }
        __syncthreads();
    }
}

extern "C" void kernel_launch(void* const* d_in, const int* in_sizes, int n_in,
                              void* d_out, int out_size) {
    const float* x      = (const float*)d_in[0];
    const float* Wx     = (const float*)d_in[1];
    const float* Wh     = (const float*)d_in[2];
    const float* b_lstm = (const float*)d_in[3];
    const float* W_head = (const float*)d_in[4];
    const float* b_head = (const float*)d_in[5];
    const float* W_out  = (const float*)d_in[6];
    const float* b_out  = (const float*)d_in[7];
    float* out = (float*)d_out;

    size_t smem = sizeof(SMem);
    cudaFuncSetAttribute(ntm_kernel, cudaFuncAttributeMaxDynamicSharedMemorySize, (int)smem);
    ntm_kernel<<<128, 1024, smem>>>(x, Wx, Wh, b_lstm, W_head, b_head, W_out, b_out, out);
}

// round 4
// speedup vs baseline: 1.4219x; 1.1201x over previous
#include <cuda_runtime.h>
#include <cooperative_groups.h>
#include <math.h>

namespace cg = cooperative_groups;

#define EPS 1e-8f
// B=64, S=64, I=64, O=64, N=1024, M=64, H=256, 4H=1024, P=268
// 4-CTA cluster handles 2 batches. Ranks {0,1} own batch A's memory (n-halves),
// ranks {2,3} own batch B's. GEMV phases are cluster-wide 2-batch GEMMs:
// rank r owns gate cols {qb*256 + 64r .. +64} (all 4 gate blocks), head cols
// [68r, 68r+68), out cols [16r, 16r+16).

struct SMem {
    float  mem[64 * 512];     // own batch's memory half, [m][nl]  (128 KB)
    float4 part[2048];        // GEMM partials (32 KB); scalar-reused
    float  wr[512], ww[512];
    float  t1[512], t2[512];
    float  h[2][2][256];      // [buf][batch][H]
    float  c[2][64];          // [batch][own 64 dims]
    float  xr[2][128];
    float  gates[2][256];     // own col slice, [batch][qb*64+jl]
    float  p[272];            // full head output for OWN batch
    float  kr[64], kw[64], e[64], a[64];
    float  rpart[64];
    float  rrecv[4][64];
    float  rvec[2][64];
    float  scal[16];          // 0..5 read head, 6=|kr|, 7=|kw|, 8..13 write head
    float  qhalo[4];          // peer boundary q: [qr@nl0, qr@nl511, qw@nl0, qw@nl511]
    float  wh_r[2], wh_w[2];  // prev-w halos: [peer nl0, peer nl511]
    float  xch[4];            // pair reduction slots
    float2 red[32];
};

__device__ __forceinline__ float sigmoidf_(float x) { return 1.f / (1.f + expf(-x)); }
__device__ __forceinline__ float softplusf_(float x) { return fmaxf(x, 0.f) + log1pf(expf(-fabsf(x))); }

__device__ __forceinline__ float2 blockReduceSum2(float2 v, float2* red) {
#pragma unroll
    for (int o = 16; o; o >>= 1) {
        v.x += __shfl_xor_sync(0xffffffffu, v.x, o);
        v.y += __shfl_xor_sync(0xffffffffu, v.y, o);
    }
    int w = threadIdx.x >> 5;
    if ((threadIdx.x & 31) == 0) red[w] = v;
    __syncthreads();
    if (threadIdx.x < 32) {
        v = red[threadIdx.x];
#pragma unroll
        for (int o = 16; o; o >>= 1) {
            v.x += __shfl_xor_sync(0xffffffffu, v.x, o);
            v.y += __shfl_xor_sync(0xffffffffu, v.y, o);
        }
        if (threadIdx.x == 0) red[0] = v;
    }
    __syncthreads();
    v = red[0];
    __syncthreads();
    return v;
}

__global__ void __launch_bounds__(1024, 1) __cluster_dims__(4, 1, 1)
ntm_kernel(const float* __restrict__ x,       // (64,64,64)
           const float* __restrict__ Wx,      // (128,1024)
           const float* __restrict__ Wh,      // (256,1024)
           const float* __restrict__ b_lstm,  // (1024)
           const float* __restrict__ W_head,  // (256,268)
           const float* __restrict__ b_head,  // (268)
           const float* __restrict__ W_out,   // (320,64)
           const float* __restrict__ b_out,   // (64)
           float* __restrict__ out)           // (64,64,64)
{
    extern __shared__ char smraw[];
    SMem* s = (SMem*)smraw;
    cg::cluster_group cl = cg::this_cluster();

    const int rank = (int)cl.block_rank();    // 0..3
    const int clid = blockIdx.x >> 2;         // 0..31
    const int t    = threadIdx.x;

    SMem* P0 = (SMem*)cl.map_shared_rank(smraw, 0);
    SMem* P1 = (SMem*)cl.map_shared_rank(smraw, 1);
    SMem* P2 = (SMem*)cl.map_shared_rank(smraw, 2);
    SMem* P3 = (SMem*)cl.map_shared_rank(smraw, 3);
    SMem* pp = (SMem*)cl.map_shared_rank(smraw, rank ^ 1);   // pair peer

    float*  partf = (float*)s->part;
    float4* mem4  = (float4*)s->mem;

    // ---- init ----
    {
        float4 iv = make_float4(0.01f, 0.01f, 0.01f, 0.01f);
#pragma unroll
        for (int i = 0; i < 8; ++i) mem4[i * 1024 + t] = iv;
        if (t < 512) { float w0 = ((rank & 1) == 0 && t == 0) ? 1.f : 0.f; s->wr[t] = w0; s->ww[t] = w0; }
        if (t < 1024) ((float*)s->h)[t] = 0.f;
        if (t < 128) ((float*)s->c)[t] = 0.f;
        if (t < 128) ((float*)s->rvec)[t] = 0.f;
        if (t == 0) {
            float hv = (rank & 1) ? 1.f : 0.f;   // peer nl0 is global n=0 for odd ranks
            s->wh_r[0] = hv; s->wh_w[0] = hv;
            s->wh_r[1] = 0.f; s->wh_w[1] = 0.f;
        }
    }
    cl.sync();

    for (int step = 0; step < 64; ++step) {
        const int prv = step & 1, cur = prv ^ 1;
        const float* hpA = s->h[prv][0];
        const float* hpB = s->h[prv][1];

        // ---- phase 1: xr[bat] = [x_t(bat), rvec(bat)] ----
        if (t < 256) {
            int bat = t >> 7, idx = t & 127;
            int bg = clid * 2 + bat;
            s->xr[bat][idx] = (idx < 64) ? x[((bg << 6) + step) * 64 + idx]
                                         : s->rvec[bat][idx - 64];
        }
        __syncthreads();

        // ---- phase 2: gates (2 batches x 384 x own-256-cols) ----
        {
            int qi = t & 63;              // (qb<<4)|qw
            int qb = qi >> 4, qw = qi & 15;
            int col4 = qb * 64 + rank * 16 + qw;
            int ch = t >> 6;              // 0..15, rows [24ch, 24ch+24)
            const float4* wx4 = (const float4*)Wx;
            const float4* wh4 = (const float4*)Wh;
            float4 aA = make_float4(0.f, 0.f, 0.f, 0.f);
            float4 aB = make_float4(0.f, 0.f, 0.f, 0.f);
            int r0 = ch * 24;
#pragma unroll 8
            for (int rr = r0; rr < r0 + 24; ++rr) {
                float4 w = (rr < 128) ? wx4[rr * 256 + col4] : wh4[(rr - 128) * 256 + col4];
                float vA = (rr < 128) ? s->xr[0][rr] : hpA[rr - 128];
                float vB = (rr < 128) ? s->xr[1][rr] : hpB[rr - 128];
                aA.x += vA * w.x; aA.y += vA * w.y; aA.z += vA * w.z; aA.w += vA * w.w;
                aB.x += vB * w.x; aB.y += vB * w.y; aB.z += vB * w.z; aB.w += vB * w.w;
            }
            s->part[t] = aA;
            s->part[1024 + t] = aB;
        }
        __syncthreads();
        if (t < 128) {
            int bat = t >> 6, qi = t & 63;
            int qb = qi >> 4, qw = qi & 15;
            int col4 = qb * 64 + rank * 16 + qw;
            float4 acc = ((const float4*)b_lstm)[col4];
#pragma unroll
            for (int ch = 0; ch < 16; ++ch) {
                float4 p0 = s->part[bat * 1024 + qi + 64 * ch];
                acc.x += p0.x; acc.y += p0.y; acc.z += p0.z; acc.w += p0.w;
            }
            ((float4*)s->gates[bat])[qi] = acc;
        }
        __syncthreads();

        // ---- phase 3: LSTM pointwise on own 64 h-dims x 2 batches; broadcast h ----
        if (t < 128) {
            int bat = t >> 6, jl = t & 63;
            float ig = s->gates[bat][jl], fg = s->gates[bat][64 + jl],
                  gg = s->gates[bat][128 + jl], og = s->gates[bat][192 + jl];
            float cc = sigmoidf_(fg) * s->c[bat][jl] + sigmoidf_(ig) * tanhf(gg);
            s->c[bat][jl] = cc;
            float hv = sigmoidf_(og) * tanhf(cc);
            int gj = rank * 64 + jl;
            P0->h[cur][bat][gj] = hv;
            P1->h[cur][bat][gj] = hv;
            P2->h[cur][bat][gj] = hv;
            P3->h[cur][bat][gj] = hv;
        }
        cl.sync();   // S1: full new h in all 4 CTAs

        // ---- phase 4: head GEMM, own 68 cols x 2 batches; scatter p to owners ----
        const float* hnA = s->h[cur][0];
        const float* hnB = s->h[cur][1];
        const int cr = (rank < 3) ? 68 : 64;
        if (t < 952) {
            int oi = t % 136, ch = t / 136;        // ch 0..6
            int j = oi % 68, bat = oi / 68;
            float acc = 0.f;
            if (j < cr) {
                int col = 68 * rank + j;
                const float* hh = bat ? hnB : hnA;
                int k0 = ch * 37, k1 = (ch == 6) ? 256 : k0 + 37;
                for (int k = k0; k < k1; ++k) acc += hh[k] * W_head[k * 268 + col];
            }
            partf[t] = acc;
        } else if (t < 1016) {
            s->rpart[t - 952] = 0.f;               // zero r accumulator
        }
        __syncthreads();
        if (t < 136) {
            int j = t % 68, bat = t / 68;
            if (j < cr) {
                int col = 68 * rank + j;
                float v = b_head[col];
#pragma unroll
                for (int k = 0; k < 7; ++k) v += partf[t + 136 * k];
                if (bat == 0) { P0->p[col] = v; P1->p[col] = v; }
                else          { P2->p[col] = v; P3->p[col] = v; }
            }
        }
        cl.sync();   // S2: full p for own batch in each pair CTA

        // ---- phase 5: parse heads (locally, duplicated within pair) ----
        if (t < 64) s->kr[t] = tanhf(s->p[t]);
        else if (t < 128) s->kw[t - 64] = tanhf(s->p[70 + t - 64]);
        else if (t < 192) s->e[t - 128] = sigmoidf_(s->p[140 + (t - 128)]);
        else if (t < 256) s->a[t - 192] = s->p[204 + (t - 192)];
        else if (t == 256) {
            s->scal[0] = softplusf_(s->p[64]);
            s->scal[1] = sigmoidf_(s->p[65]);
            float a0 = s->p[66], a1 = s->p[67], a2 = s->p[68];
            float mx = fmaxf(a0, fmaxf(a1, a2));
            float e0 = expf(a0 - mx), e1 = expf(a1 - mx), e2 = expf(a2 - mx);
            float sm = e0 + e1 + e2;
            s->scal[2] = e0 / sm; s->scal[3] = e1 / sm; s->scal[4] = e2 / sm;
            s->scal[5] = 1.f + softplusf_(s->p[69]);
        } else if (t == 288) {
            s->scal[8] = softplusf_(s->p[134]);
            s->scal[9] = sigmoidf_(s->p[135]);
            float a0 = s->p[136], a1 = s->p[137], a2 = s->p[138];
            float mx = fmaxf(a0, fmaxf(a1, a2));
            float e0 = expf(a0 - mx), e1 = expf(a1 - mx), e2 = expf(a2 - mx);
            float sm = e0 + e1 + e2;
            s->scal[10] = e0 / sm; s->scal[11] = e1 / sm; s->scal[12] = e2 / sm;
            s->scal[13] = 1.f + softplusf_(s->p[139]);
        }
        __syncthreads();
        if (t < 32) {
            float v = s->kr[t] * s->kr[t] + s->kr[t + 32] * s->kr[t + 32];
#pragma unroll
            for (int o = 16; o; o >>= 1) v += __shfl_xor_sync(0xffffffffu, v, o);
            if (t == 0) s->scal[6] = sqrtf(v);
        } else if (t < 64) {
            int l = t - 32;
            float v = s->kw[l] * s->kw[l] + s->kw[l + 32] * s->kw[l + 32];
#pragma unroll
            for (int o = 16; o; o >>= 1) v += __shfl_xor_sync(0xffffffffu, v, o);
            if (l == 0) s->scal[7] = sqrtf(v);
        }
        __syncthreads();

        // ---- phase 6: addressing over own 512 n-rows (mem in SMEM) ----
        const int nl = t & 511, mh = t >> 9;
        {
            float dr = 0.f, dw = 0.f, nn = 0.f;
            int m0 = mh * 32;
#pragma unroll 8
            for (int m = m0; m < m0 + 32; ++m) {
                float v = s->mem[m * 512 + nl];
                dr += s->kr[m] * v;
                dw += s->kw[m] * v;
                nn += v * v;
            }
            s->part[t] = make_float4(dr, dw, nn, 0.f);
        }
        __syncthreads();
        const bool lead = (t < 512);
        float qr = 0.f, qw = 0.f, er = 0.f, ew = 0.f;
        if (lead) {
            float4 p0 = s->part[t], p1 = s->part[t + 512];
            float dr = p0.x + p1.x, dw = p0.y + p1.y, nn = p0.z + p1.z;
            float nrm = sqrtf(nn);
            qr = s->scal[0] * (dr / (s->scal[6] * nrm + EPS));
            qw = s->scal[8] * (dw / (s->scal[7] * nrm + EPS));
            if (nl == 0)   { pp->qhalo[0] = qr; pp->qhalo[2] = qw; }
            if (nl == 511) { pp->qhalo[1] = qr; pp->qhalo[3] = qw; }
            er = expf(qr);          // |q| <= beta <= ~14: overflow-safe, max-shift dropped
            ew = expf(qw);
        }
        float2 lsum = blockReduceSum2(make_float2(er, ew), s->red);
        if (t == 0) { pp->xch[0] = lsum.x; pp->xch[1] = lsum.y; }
        cl.sync();   // S3: exp-sums + boundary q exchanged within pair
        const float gsr = lsum.x + s->xch[0];
        const float gsw = lsum.y + s->xch[1];
        const float g_r = s->scal[1], g_w = s->scal[9];
        if (lead) {
            float wgr = g_r * (er / gsr) + (1.f - g_r) * s->wr[nl];
            float wgw = g_w * (ew / gsw) + (1.f - g_w) * s->ww[nl];
            s->t1[nl] = wgr;
            s->t2[nl] = wgw;
        }
        __syncthreads();
        float wpr = 0.f, wpw = 0.f;
        if (lead) {
            // halo wg values computed locally from peer boundary q + prev-w halos
            float t1p = (nl == 511) ? (g_r * (expf(s->qhalo[0]) / gsr) + (1.f - g_r) * s->wh_r[0]) : s->t1[nl + 1];
            float t1m = (nl == 0)   ? (g_r * (expf(s->qhalo[1]) / gsr) + (1.f - g_r) * s->wh_r[1]) : s->t1[nl - 1];
            float t2p = (nl == 511) ? (g_w * (expf(s->qhalo[2]) / gsw) + (1.f - g_w) * s->wh_w[0]) : s->t2[nl + 1];
            float t2m = (nl == 0)   ? (g_w * (expf(s->qhalo[3]) / gsw) + (1.f - g_w) * s->wh_w[1]) : s->t2[nl - 1];
            float wsr = s->scal[2]  * t1p + s->scal[3]  * s->t1[nl] + s->scal[4]  * t1m;
            float wsw = s->scal[10] * t2p + s->scal[11] * s->t2[nl] + s->scal[12] * t2m;
            wpr = (wsr > 0.f) ? expf(s->scal[5]  * logf(wsr)) : 0.f;
            wpw = (wsw > 0.f) ? expf(s->scal[13] * logf(wsw)) : 0.f;
        }
        float2 lsp = blockReduceSum2(make_float2(wpr, wpw), s->red);
        if (t == 0) { pp->xch[2] = lsp.x; pp->xch[3] = lsp.y; }
        cl.sync();   // S4: sharpen sums exchanged within pair
        if (lead) {
            float wrv = wpr / ((lsp.x + s->xch[2]) + EPS);
            float wwv = wpw / ((lsp.y + s->xch[3]) + EPS);
            s->wr[nl] = wrv;
            s->ww[nl] = wwv;
            // push new boundary w to peer's prev-w halos for next step (ordered by S5)
            if (nl == 0)   { pp->wh_r[0] = wrv; pp->wh_w[0] = wwv; }
            if (nl == 511) { pp->wh_r[1] = wrv; pp->wh_w[1] = wwv; }
        }
        __syncthreads();

        // ---- phase 7: fused read (old mem) + erase/add update ----
        {
            int n4 = t & 127, mch = t >> 7;
            float4 wr4 = ((const float4*)s->wr)[n4];
            float4 ww4 = ((const float4*)s->ww)[n4];
#pragma unroll 4
            for (int mi = 0; mi < 8; ++mi) {
                int m = mch * 8 + mi;
                float em = s->e[m], am = s->a[m];
                float4 v = mem4[m * 128 + n4];
                float rp = wr4.x * v.x + wr4.y * v.y + wr4.z * v.z + wr4.w * v.w;
                v.x = v.x * (1.f - ww4.x * em) + ww4.x * am;
                v.y = v.y * (1.f - ww4.y * em) + ww4.y * am;
                v.z = v.z * (1.f - ww4.z * em) + ww4.z * am;
                v.w = v.w * (1.f - ww4.w * em) + ww4.w * am;
                mem4[m * 128 + n4] = v;
#pragma unroll
                for (int o = 16; o; o >>= 1) rp += __shfl_xor_sync(0xffffffffu, rp, o);
                if ((t & 31) == 0) atomicAdd(&s->rpart[m], rp);
            }
        }
        __syncthreads();
        if (t < 64) {   // broadcast r partial to all 4 CTAs
            float v = s->rpart[t];
            P0->rrecv[rank][t] = v;
            P1->rrecv[rank][t] = v;
            P2->rrecv[rank][t] = v;
            P3->rrecv[rank][t] = v;
        }
        cl.sync();   // S5: r partials everywhere (+ w halos ordered)
        if (t < 128) {
            int bat = t >> 6, i = t & 63;
            s->rvec[bat][i] = s->rrecv[bat * 2][i] + s->rrecv[bat * 2 + 1][i];
        }
        __syncthreads();

        // ---- phase 8: out GEMM, own 16 cols x 2 batches ----
        {
            int oi = t & 31, ch = t >> 5;          // 32 chunks x 10 rows
            int bat = oi >> 4, jc = oi & 15;
            int col = 16 * rank + jc;
            const float* hh = bat ? hnB : hnA;
            float acc = 0.f;
            int r0 = ch * 10;
#pragma unroll
            for (int rr = r0; rr < r0 + 10; ++rr) {
                float v = (rr < 256) ? hh[rr] : s->rvec[bat][rr - 256];
                acc += v * W_out[rr * 64 + col];
            }
            partf[t] = acc;
        }
        __syncthreads();
        if (t < 32) {
            int bat = t >> 4, jc = t & 15;
            int col = 16 * rank + jc;
            float acc = b_out[col];
#pragma unroll
            for (int ch = 0; ch < 32; ++ch) acc += partf[t + 32 * ch];
            int bg = clid * 2 + bat;
            out[((bg << 6) + step) * 64 + col] = acc;
        }
        __syncthreads();
    }
}

extern "C" void kernel_launch(void* const* d_in, const int* in_sizes, int n_in,
                              void* d_out, int out_size) {
    const float* x      = (const float*)d_in[0];
    const float* Wx     = (const float*)d_in[1];
    const float* Wh     = (const float*)d_in[2];
    const float* b_lstm = (const float*)d_in[3];
    const float* W_head = (const float*)d_in[4];
    const float* b_head = (const float*)d_in[5];
    const float* W_out  = (const float*)d_in[6];
    const float* b_out  = (const float*)d_in[7];
    float* out = (float*)d_out;

    size_t smem = sizeof(SMem);
    cudaFuncSetAttribute(ntm_kernel, cudaFuncAttributeMaxDynamicSharedMemorySize, (int)smem);
    ntm_kernel<<<128, 1024, smem>>>(x, Wx, Wh, b_lstm, W_head, b_head, W_out, b_out, out);
}